// round 7
// baseline (speedup 1.0000x reference)
#include <cuda_runtime.h>
#include <cuda_bf16.h>
#include <cstdint>

// Problem constants
#define DD    128
#define NMAX  50000
#define EMAX  800000

// bf16 smem row stride (128 data + 4 pad) to break LDS bank aliasing
#define ASTR  132
#define TILE_BF16 (128 * ASTR)              // bf16 elements per tile
#define GSM_BYTES (4 * TILE_BF16 * 2)       // ah, al, bh, bl

// -------- scratch (allocation-free: __device__ globals) --------
__device__ float g_bufs[4ull * NMAX * DD];  // xn, agg, h, xraw
// [0:128) colsum  [128:256) colsumsq  [256:384) bn scale  [384:512) bn shift
__device__ __align__(16) float g_small[512];
__device__ int g_edge64;
// CSR scratch
__device__ int g_sorted_src[EMAX];
__device__ int g_rowoff[NMAX + 1];
__device__ int g_counts[NMAX];
__device__ int g_partials[1024];
// pre-split W^T images: 6 slots (W1 l0..2 then W2 l0..2), each [hi 16384][lo 16384]
// plain row-major Bt[n][k] bf16
__device__ __align__(16) __nv_bfloat16 g_wt[6][2][16384];

// ================= utility / CSR kernels =================
__global__ void zero_stats_kernel() { g_small[threadIdx.x] = 0.0f; }

__global__ void zero_counts_kernel(int n) {
    int i = blockIdx.x * blockDim.x + threadIdx.x;
    if (i < n) g_counts[i] = 0;
}

__global__ void detect_kernel(const int* __restrict__ ei) {
    if (threadIdx.x == 0) {
        int ok = 1;
        for (int i = 0; i < 256; i++)
            if (ei[2 * i + 1] != 0) { ok = 0; break; }
        g_edge64 = ok;
    }
}

__device__ __forceinline__ void load_edge(const void* ei, int E, int e, int& s, int& d) {
    if (g_edge64) {
        const long long* e64 = (const long long*)ei;
        s = (int)e64[e]; d = (int)e64[E + e];
    } else {
        const int* e32 = (const int*)ei;
        s = e32[e]; d = e32[E + e];
    }
}

__global__ void hist_kernel(const void* __restrict__ ei, int E) {
    int e = blockIdx.x * blockDim.x + threadIdx.x;
    if (e >= E) return;
    int s, d; load_edge(ei, E, e, s, d);
    atomicAdd(&g_counts[d], 1);
}

__global__ void scanA_kernel(int n) {
    __shared__ int sm[256];
    int t = threadIdx.x;
    int i = blockIdx.x * 256 + t;
    int v = (i < n) ? g_counts[i] : 0;
    sm[t] = v;
    __syncthreads();
#pragma unroll
    for (int off = 1; off < 256; off <<= 1) {
        int add = (t >= off) ? sm[t - off] : 0;
        __syncthreads();
        sm[t] += add;
        __syncthreads();
    }
    if (i < n) g_rowoff[i] = sm[t] - v;
    if (t == 255) g_partials[blockIdx.x] = sm[t];
}

__global__ void scanB_kernel(int nb) {
    __shared__ int sm[1024];
    int t = threadIdx.x;
    int v = (t < nb) ? g_partials[t] : 0;
    sm[t] = v;
    __syncthreads();
#pragma unroll
    for (int off = 1; off < 1024; off <<= 1) {
        int add = (t >= off) ? sm[t - off] : 0;
        __syncthreads();
        sm[t] += add;
        __syncthreads();
    }
    if (t < nb) g_partials[t] = sm[t] - v;
}

__global__ void scanC2_kernel(int n) {
    int i = blockIdx.x * 256 + threadIdx.x;
    if (i < n) g_rowoff[i] += g_partials[blockIdx.x];
}

__global__ void place_kernel(const void* __restrict__ ei, int E) {
    int e = blockIdx.x * blockDim.x + threadIdx.x;
    if (e >= E) return;
    int s, d; load_edge(ei, E, e, s, d);
    int pos = atomicAdd(&g_rowoff[d], 1);
    g_sorted_src[pos] = s;
}

__global__ void prep_kernel(const float* __restrict__ raw,
                            float* __restrict__ xn, int n) {
    int idx = blockIdx.x * blockDim.x + threadIdx.x;
    int total = n * (DD / 4);
    if (idx >= total) return;
    float4 v = ((const float4*)raw)[idx];
    int c4 = idx & 31;
    float4 s = ((const float4*)(g_small + 256))[c4];
    float4 t = ((const float4*)(g_small + 384))[c4];
    v.x = fmaxf(fmaf(v.x, s.x, t.x), 0.0f);
    v.y = fmaxf(fmaf(v.y, s.y, t.y), 0.0f);
    v.z = fmaxf(fmaf(v.z, s.z, t.z), 0.0f);
    v.w = fmaxf(fmaf(v.w, s.w, t.w), 0.0f);
    ((float4*)xn)[idx] = v;
}

__global__ void agg_kernel(const float* __restrict__ xn,
                           float* __restrict__ agg,
                           const float* __restrict__ epsArr,
                           int layer, int n) {
    int node = (blockIdx.x * blockDim.x + threadIdx.x) >> 5;
    int lane = threadIdx.x & 31;
    if (node >= n) return;
    int start = (node == 0) ? 0 : g_rowoff[node - 1];
    int end = g_rowoff[node];
    const float4* X4 = (const float4*)xn;
    float e1 = 1.0f + epsArr[layer];
    float4 self = X4[(size_t)node * 32 + lane];
    float ax = self.x * e1, ay = self.y * e1, az = self.z * e1, aw = self.w * e1;
    int e = start;
    for (; e + 4 <= end; e += 4) {
        int s0 = g_sorted_src[e];
        int s1 = g_sorted_src[e + 1];
        int s2 = g_sorted_src[e + 2];
        int s3 = g_sorted_src[e + 3];
        float4 v0 = X4[(size_t)s0 * 32 + lane];
        float4 v1 = X4[(size_t)s1 * 32 + lane];
        float4 v2 = X4[(size_t)s2 * 32 + lane];
        float4 v3 = X4[(size_t)s3 * 32 + lane];
        ax += v0.x + v1.x + v2.x + v3.x;
        ay += v0.y + v1.y + v2.y + v3.y;
        az += v0.z + v1.z + v2.z + v3.z;
        aw += v0.w + v1.w + v2.w + v3.w;
    }
    for (; e < end; e++) {
        int s0 = g_sorted_src[e];
        float4 v0 = X4[(size_t)s0 * 32 + lane];
        ax += v0.x; ay += v0.y; az += v0.z; aw += v0.w;
    }
    ((float4*)agg)[(size_t)node * 32 + lane] = make_float4(ax, ay, az, aw);
}

// ================= weight prep: W[k,n] -> Bt[n,k] hi/lo (plain row-major) ========
// grid = 6 blocks, 128 threads (thread = output column n)
__global__ void wprep_kernel(const float* __restrict__ W1,
                             const float* __restrict__ W2) {
    int slot = blockIdx.x;
    const float* W = (slot < 3) ? (W1 + (size_t)slot * DD * DD)
                                : (W2 + (size_t)(slot - 3) * DD * DD);
    __nv_bfloat16* hiB = &g_wt[slot][0][0];
    __nv_bfloat16* loB = &g_wt[slot][1][0];
    int nrow = threadIdx.x;
    for (int k = 0; k < 128; k += 2) {
        float w0 = W[(size_t)k * 128 + nrow];
        float w1 = W[(size_t)(k + 1) * 128 + nrow];
        uint32_t hp;
        asm("cvt.rn.satfinite.bf16x2.f32 %0, %1, %2;" : "=r"(hp) : "f"(w1), "f"(w0));
        float h0 = __uint_as_float(hp << 16);
        float h1 = __uint_as_float(hp & 0xffff0000u);
        float l0 = w0 - h0, l1 = w1 - h1;
        uint32_t lp;
        asm("cvt.rn.satfinite.bf16x2.f32 %0, %1, %2;" : "=r"(lp) : "f"(l1), "f"(l0));
        *(uint32_t*)&hiB[nrow * 128 + k] = hp;
        *(uint32_t*)&loB[nrow * 128 + k] = lp;
    }
}

// ================= bf16-split tensor-core GEMM (mma.sync m16n8k16) ==============
// out[n,128] = act(A)[n,128] @ W + bias; W given pre-split as Bt[n][k] hi|lo.
// 256 threads = 8 warps (4 M x 2 N); warp tile 32x64; 3 passes ah*bh+al*bh+ah*bl.
__device__ __forceinline__ void mma16816(float* c, const uint32_t* a,
                                         uint32_t b0, uint32_t b1) {
    asm volatile(
        "mma.sync.aligned.m16n8k16.row.col.f32.bf16.bf16.f32 "
        "{%0,%1,%2,%3}, {%4,%5,%6,%7}, {%8,%9}, {%0,%1,%2,%3};"
        : "+f"(c[0]), "+f"(c[1]), "+f"(c[2]), "+f"(c[3])
        : "r"(a[0]), "r"(a[1]), "r"(a[2]), "r"(a[3]), "r"(b0), "r"(b1));
}

__global__ __launch_bounds__(256, 1)
void tc_gemm_kernel(const float* __restrict__ A,
                    const __nv_bfloat16* __restrict__ Wt,   // [2][16384] hi|lo
                    const float* __restrict__ bias,
                    float* __restrict__ out,
                    int n, int applyBN) {
    extern __shared__ __nv_bfloat16 sm[];
    __nv_bfloat16* ah = sm;
    __nv_bfloat16* al = ah + TILE_BF16;
    __nv_bfloat16* bh = al + TILE_BF16;
    __nv_bfloat16* bl = bh + TILE_BF16;

    int tid = threadIdx.x;
    int warp = tid >> 5;
    int lane = tid & 31;
    int rowBase = blockIdx.x << 7;

    // ---- load B hi/lo images (plain [n][128]) into padded smem ----
    {
        const uint32_t* WH = (const uint32_t*)Wt;       // 8192 u32
        const uint32_t* WL = WH + 8192;
#pragma unroll
        for (int i = 0; i < 32; i++) {
            int idx = tid + 256 * i;        // 0..8191
            int r = idx >> 6;               // n row
            int c = idx & 63;               // u32 col (k pair)
            *(uint32_t*)&bh[r * ASTR + 2 * c] = WH[idx];
            *(uint32_t*)&bl[r * ASTR + 2 * c] = WL[idx];
        }
    }

    // ---- load A tile (fp32 -> split bf16 hi/lo), BN fused ----
    {
        int row = tid >> 1;                 // 0..127
        int half = tid & 1;                 // which 64-col half
        int grow = rowBase + row;
        const float4* A4 = (const float4*)A;
#pragma unroll
        for (int j = 0; j < 16; j++) {
            int c4 = half * 16 + j;         // float4 col 0..31
            float4 v = make_float4(0.f, 0.f, 0.f, 0.f);
            if (grow < n) v = A4[(size_t)grow * 32 + c4];
            if (applyBN) {
                float4 s = ((const float4*)(g_small + 256))[c4];
                float4 t = ((const float4*)(g_small + 384))[c4];
                v.x = fmaxf(fmaf(v.x, s.x, t.x), 0.0f);
                v.y = fmaxf(fmaf(v.y, s.y, t.y), 0.0f);
                v.z = fmaxf(fmaf(v.z, s.z, t.z), 0.0f);
                v.w = fmaxf(fmaf(v.w, s.w, t.w), 0.0f);
            }
            uint32_t hp0, hp1;
            asm("cvt.rn.satfinite.bf16x2.f32 %0, %1, %2;" : "=r"(hp0) : "f"(v.y), "f"(v.x));
            asm("cvt.rn.satfinite.bf16x2.f32 %0, %1, %2;" : "=r"(hp1) : "f"(v.w), "f"(v.z));
            float l0 = v.x - __uint_as_float(hp0 << 16);
            float l1 = v.y - __uint_as_float(hp0 & 0xffff0000u);
            float l2 = v.z - __uint_as_float(hp1 << 16);
            float l3 = v.w - __uint_as_float(hp1 & 0xffff0000u);
            uint32_t lp0, lp1;
            asm("cvt.rn.satfinite.bf16x2.f32 %0, %1, %2;" : "=r"(lp0) : "f"(l1), "f"(l0));
            asm("cvt.rn.satfinite.bf16x2.f32 %0, %1, %2;" : "=r"(lp1) : "f"(l3), "f"(l2));
            int col = 4 * c4;
            *(uint32_t*)&ah[row * ASTR + col]     = hp0;
            *(uint32_t*)&ah[row * ASTR + col + 2] = hp1;
            *(uint32_t*)&al[row * ASTR + col]     = lp0;
            *(uint32_t*)&al[row * ASTR + col + 2] = lp1;
        }
    }
    __syncthreads();

    // ---- warp MMA ----
    int warpM = warp >> 1;                  // 0..3 -> rows warpM*32
    int warpN = warp & 1;                   // 0..1 -> cols warpN*64
    int g = lane >> 2;                      // 0..7
    int tig = lane & 3;                     // 0..3

    float acc[2][8][4];
#pragma unroll
    for (int mi = 0; mi < 2; mi++)
#pragma unroll
        for (int ni = 0; ni < 8; ni++)
#pragma unroll
            for (int q = 0; q < 4; q++) acc[mi][ni][q] = 0.0f;

#pragma unroll
    for (int pass = 0; pass < 3; pass++) {
        const __nv_bfloat16* As = (pass == 1) ? al : ah;
        const __nv_bfloat16* Bs = (pass == 2) ? bl : bh;
#pragma unroll
        for (int k = 0; k < 128; k += 16) {
            uint32_t afrag[2][4];
#pragma unroll
            for (int mi = 0; mi < 2; mi++) {
                int r0 = warpM * 32 + mi * 16 + g;
                afrag[mi][0] = *(const uint32_t*)&As[r0 * ASTR + k + 2 * tig];
                afrag[mi][1] = *(const uint32_t*)&As[(r0 + 8) * ASTR + k + 2 * tig];
                afrag[mi][2] = *(const uint32_t*)&As[r0 * ASTR + k + 8 + 2 * tig];
                afrag[mi][3] = *(const uint32_t*)&As[(r0 + 8) * ASTR + k + 8 + 2 * tig];
            }
#pragma unroll
            for (int ni = 0; ni < 8; ni++) {
                int nc = warpN * 64 + ni * 8 + g;   // B row (output col group)
                uint32_t b0 = *(const uint32_t*)&Bs[nc * ASTR + k + 2 * tig];
                uint32_t b1 = *(const uint32_t*)&Bs[nc * ASTR + k + 8 + 2 * tig];
                mma16816(acc[0][ni], afrag[0], b0, b1);
                mma16816(acc[1][ni], afrag[1], b0, b1);
            }
        }
    }

    // ---- epilogue: bias + store ----
#pragma unroll
    for (int mi = 0; mi < 2; mi++) {
        int r0 = rowBase + warpM * 32 + mi * 16 + g;
#pragma unroll
        for (int ni = 0; ni < 8; ni++) {
            int col = warpN * 64 + ni * 8 + 2 * tig;
            float bx = bias[col], by = bias[col + 1];
            if (r0 < n) {
                float2 o = make_float2(acc[mi][ni][0] + bx, acc[mi][ni][1] + by);
                *(float2*)&out[(size_t)r0 * DD + col] = o;
            }
            if (r0 + 8 < n) {
                float2 o = make_float2(acc[mi][ni][2] + bx, acc[mi][ni][3] + by);
                *(float2*)&out[(size_t)(r0 + 8) * DD + col] = o;
            }
        }
    }
}

// ================= column stats over output (sum, sumsq -> g_small) =============
__global__ void colstats_kernel(const float* __restrict__ h, int n) {
    __shared__ float4 rs[8][32], rq[8][32];
    int tid = threadIdx.x;
    int j = tid & 31;
    int rg = tid >> 5;
    const float4* H4 = (const float4*)h;
    float4 s = make_float4(0.f, 0.f, 0.f, 0.f);
    float4 q = make_float4(0.f, 0.f, 0.f, 0.f);
    for (int r = blockIdx.x * 8 + rg; r < n; r += gridDim.x * 8) {
        float4 v = H4[(size_t)r * 32 + j];
        s.x += v.x; s.y += v.y; s.z += v.z; s.w += v.w;
        q.x += v.x * v.x; q.y += v.y * v.y; q.z += v.z * v.z; q.w += v.w * v.w;
    }
    rs[rg][j] = s; rq[rg][j] = q;
    __syncthreads();
    if (tid < 32) {
        float4 a = rs[0][tid];
#pragma unroll
        for (int t = 1; t < 8; t++) {
            float4 b = rs[t][tid];
            a.x += b.x; a.y += b.y; a.z += b.z; a.w += b.w;
        }
        atomicAdd(&g_small[4 * tid + 0], a.x);
        atomicAdd(&g_small[4 * tid + 1], a.y);
        atomicAdd(&g_small[4 * tid + 2], a.z);
        atomicAdd(&g_small[4 * tid + 3], a.w);
    } else if (tid < 64) {
        int c = tid - 32;
        float4 a = rq[0][c];
#pragma unroll
        for (int t = 1; t < 8; t++) {
            float4 b = rq[t][c];
            a.x += b.x; a.y += b.y; a.z += b.z; a.w += b.w;
        }
        atomicAdd(&g_small[128 + 4 * c + 0], a.x);
        atomicAdd(&g_small[128 + 4 * c + 1], a.y);
        atomicAdd(&g_small[128 + 4 * c + 2], a.z);
        atomicAdd(&g_small[128 + 4 * c + 3], a.w);
    }
}

__global__ void bnparams_kernel(const float* __restrict__ gamma,
                                const float* __restrict__ beta,
                                float invN) {
    int c = threadIdx.x;
    float mean = g_small[c] * invN;
    float var = g_small[128 + c] * invN - mean * mean;
    float sc = gamma[c] * rsqrtf(fmaxf(var, 0.0f) + 1e-5f);
    g_small[256 + c] = sc;
    g_small[384 + c] = beta[c] - mean * sc;
    g_small[c] = 0.0f;
    g_small[128 + c] = 0.0f;
}

// ================= host =================
extern "C" void kernel_launch(void* const* d_in, const int* in_sizes, int n_in,
                              void* d_out, int out_size) {
    const float* x     = (const float*)d_in[0];
    const void*  ei    = d_in[1];
    const float* eps   = (const float*)d_in[2];
    const float* W1    = (const float*)d_in[3];
    const float* b1    = (const float*)d_in[4];
    const float* g1    = (const float*)d_in[5];
    const float* beta1 = (const float*)d_in[6];
    const float* W2    = (const float*)d_in[7];
    const float* b2    = (const float*)d_in[8];
    const float* bng   = (const float*)d_in[9];
    const float* bnb   = (const float*)d_in[10];
    float* out = (float*)d_out;

    int n = in_sizes[0] / DD;
    int E = in_sizes[1] / 2;

    float* bufs = nullptr;
    cudaGetSymbolAddress((void**)&bufs, g_bufs);
    float* xn   = bufs;
    float* agg  = bufs + (size_t)1 * NMAX * DD;
    float* h    = bufs + (size_t)2 * NMAX * DD;
    float* xraw = bufs + (size_t)3 * NMAX * DD;

    __nv_bfloat16* wt = nullptr;
    cudaGetSymbolAddress((void**)&wt, g_wt);

    cudaFuncSetAttribute((const void*)tc_gemm_kernel,
                         cudaFuncAttributeMaxDynamicSharedMemorySize, GSM_BYTES);

    int nb256 = (n + 255) / 256;
    int eb256 = (E + 255) / 256;

    zero_stats_kernel<<<1, 256>>>();
    detect_kernel<<<1, 32>>>((const int*)ei);
    zero_counts_kernel<<<nb256, 256>>>(n);
    hist_kernel<<<eb256, 256>>>(ei, E);
    scanA_kernel<<<nb256, 256>>>(n);
    scanB_kernel<<<1, 1024>>>(nb256);
    scanC2_kernel<<<nb256, 256>>>(n);
    place_kernel<<<eb256, 256>>>(ei, E);
    wprep_kernel<<<6, 128>>>(W1, W2);

    int prepBlocks = (n * (DD / 4) + 255) / 256;
    int aggBlocks = (n + 7) / 8;
    int gemmBlocks = (n + 127) / 128;
    float invN = 1.0f / (float)n;

    for (int layer = 0; layer < 3; layer++) {
        const float* cur = (layer == 0) ? x : xn;
        if (layer > 0) prep_kernel<<<prepBlocks, 256>>>(xraw, xn, n);
        agg_kernel<<<aggBlocks, 256>>>(cur, agg, eps, layer, n);
        tc_gemm_kernel<<<gemmBlocks, 256, GSM_BYTES>>>(
            agg, wt + (size_t)layer * 2 * 16384, b1 + layer * DD, h, n, 0);
        colstats_kernel<<<256, 256>>>(h, n);
        bnparams_kernel<<<1, 128>>>(g1 + layer * DD, beta1 + layer * DD, invN);
        int last = (layer == 2);
        float* o = last ? out : xraw;
        tc_gemm_kernel<<<gemmBlocks, 256, GSM_BYTES>>>(
            h, wt + (size_t)(3 + layer) * 2 * 16384, b2 + layer * DD, o, n, 1);
        if (!last) {
            colstats_kernel<<<256, 256>>>(o, n);
            bnparams_kernel<<<1, 128>>>(bng + layer * DD, bnb + layer * DD, invN);
        }
    }
}

// round 9
// speedup vs baseline: 1.0878x; 1.0878x over previous
#include <cuda_runtime.h>
#include <cstdint>

// Problem constants (shape-fixed per problem instance)
#define DD    128
#define NMAX  50000
#define EMAX  800000
#define GEMM_SMEM_FLOATS (16384 + 16384)
#define GEMM_SMEM_BYTES  (GEMM_SMEM_FLOATS * 4)

// -------- scratch (allocation-free: __device__ globals) --------
__device__ float g_bufs[4ull * NMAX * DD];  // xn, agg, h, xraw
// [0:128) colsum  [128:256) colsumsq  [256:384) bn scale  [384:512) bn shift
__device__ __align__(16) float g_small[512];
__device__ int g_edge64;
// CSR scratch
__device__ int g_sorted_src[EMAX];
__device__ int g_rowoff[NMAX + 1];   // becomes END offsets after placement
__device__ int g_counts[NMAX];
__device__ int g_partials[1024];

// -------- setup: zero counts + zero stats + parallel dtype detect --------
__global__ void setup_kernel(const int* __restrict__ ei, int n) {
    int i = blockIdx.x * 256 + threadIdx.x;
    if (i < n) g_counts[i] = 0;
    if (blockIdx.x == 0) {
        int t = threadIdx.x;
        g_small[t] = 0.0f;               // zero colsum + colsumsq
        __shared__ int ok;
        if (t == 0) ok = 1;
        __syncthreads();
        // int64 node ids < 2^31 -> every odd int32 word is zero
        if (ei[2 * t + 1] != 0) atomicExch(&ok, 0);
        __syncthreads();
        if (t == 0) g_edge64 = ok;
    }
}

// ---- counting sort of edges by dst (built once per launch) ----
// grid-stride, ~8 edges/thread for memory-level parallelism
__global__ void hist_kernel(const void* __restrict__ ei, int E) {
    int base = blockIdx.x * blockDim.x + threadIdx.x;
    int stride = gridDim.x * blockDim.x;
    if (g_edge64) {
        const long long* dstp = (const long long*)ei + E;
        for (int e = base; e < E; e += stride)
            atomicAdd(&g_counts[(int)dstp[e]], 1);
    } else {
        const int* dstp = (const int*)ei + E;
        for (int e = base; e < E; e += stride)
            atomicAdd(&g_counts[dstp[e]], 1);
    }
}

// block-local exclusive scan of counts -> g_rowoff; block sums -> g_partials
__global__ void scanA_kernel(int n) {
    __shared__ int sm[256];
    int t = threadIdx.x;
    int i = blockIdx.x * 256 + t;
    int v = (i < n) ? g_counts[i] : 0;
    sm[t] = v;
    __syncthreads();
#pragma unroll
    for (int off = 1; off < 256; off <<= 1) {
        int add = (t >= off) ? sm[t - off] : 0;
        __syncthreads();
        sm[t] += add;
        __syncthreads();
    }
    if (i < n) g_rowoff[i] = sm[t] - v;       // exclusive, block-local
    if (t == 255) g_partials[blockIdx.x] = sm[t];
}

// exclusive scan of block partials (NB <= 1024), single block of 1024
__global__ void scanB_kernel(int nb) {
    __shared__ int sm[1024];
    int t = threadIdx.x;
    int v = (t < nb) ? g_partials[t] : 0;
    sm[t] = v;
    __syncthreads();
#pragma unroll
    for (int off = 1; off < 1024; off <<= 1) {
        int add = (t >= off) ? sm[t - off] : 0;
        __syncthreads();
        sm[t] += add;
        __syncthreads();
    }
    if (t < nb) g_partials[t] = sm[t] - v;    // exclusive
}

__global__ void scanC2_kernel(int n) {
    int i = blockIdx.x * 256 + threadIdx.x;
    if (i < n) g_rowoff[i] += g_partials[blockIdx.x];
}

// place edges: pos = old rowoff cursor; rowoff becomes END offsets afterwards
__global__ void place_kernel(const void* __restrict__ ei, int E) {
    int base = blockIdx.x * blockDim.x + threadIdx.x;
    int stride = gridDim.x * blockDim.x;
    if (g_edge64) {
        const long long* e64 = (const long long*)ei;
        for (int e = base; e < E; e += stride) {
            int s = (int)e64[e];
            int d = (int)e64[E + e];
            g_sorted_src[atomicAdd(&g_rowoff[d], 1)] = s;
        }
    } else {
        const int* e32 = (const int*)ei;
        for (int e = base; e < E; e += stride) {
            int s = e32[e];
            int d = e32[E + e];
            g_sorted_src[atomicAdd(&g_rowoff[d], 1)] = s;
        }
    }
}

// prep: xn = BN+ReLU(raw) for layers > 0 (layer 0 uses x directly)
__global__ void prep_kernel(const float* __restrict__ raw,
                            float* __restrict__ xn, int n) {
    int idx = blockIdx.x * blockDim.x + threadIdx.x;
    int total = n * (DD / 4);
    if (idx >= total) return;
    float4 v = ((const float4*)raw)[idx];
    int c4 = idx & 31;
    float4 s = ((const float4*)(g_small + 256))[c4];
    float4 t = ((const float4*)(g_small + 384))[c4];
    v.x = fmaxf(fmaf(v.x, s.x, t.x), 0.0f);
    v.y = fmaxf(fmaf(v.y, s.y, t.y), 0.0f);
    v.z = fmaxf(fmaf(v.z, s.z, t.z), 0.0f);
    v.w = fmaxf(fmaf(v.w, s.w, t.w), 0.0f);
    ((float4*)xn)[idx] = v;
}

// gather aggregation: one warp per dst node.
// agg[i] = (1+eps)*xn[i] + sum_{e in CSR row i} xn[src[e]]
__global__ void agg_kernel(const float* __restrict__ xn,
                           float* __restrict__ agg,
                           const float* __restrict__ epsArr,
                           int layer, int n) {
    int node = (blockIdx.x * blockDim.x + threadIdx.x) >> 5;
    int lane = threadIdx.x & 31;
    if (node >= n) return;
    int start = (node == 0) ? 0 : g_rowoff[node - 1];
    int end = g_rowoff[node];
    const float4* X4 = (const float4*)xn;
    float e1 = 1.0f + epsArr[layer];
    float4 self = X4[(size_t)node * 32 + lane];
    float ax = self.x * e1, ay = self.y * e1, az = self.z * e1, aw = self.w * e1;
    int e = start;
    for (; e + 4 <= end; e += 4) {
        int s0 = g_sorted_src[e];
        int s1 = g_sorted_src[e + 1];
        int s2 = g_sorted_src[e + 2];
        int s3 = g_sorted_src[e + 3];
        float4 v0 = X4[(size_t)s0 * 32 + lane];
        float4 v1 = X4[(size_t)s1 * 32 + lane];
        float4 v2 = X4[(size_t)s2 * 32 + lane];
        float4 v3 = X4[(size_t)s3 * 32 + lane];
        ax += v0.x + v1.x + v2.x + v3.x;
        ay += v0.y + v1.y + v2.y + v3.y;
        az += v0.z + v1.z + v2.z + v3.z;
        aw += v0.w + v1.w + v2.w + v3.w;
    }
    for (; e < end; e++) {
        int s0 = g_sorted_src[e];
        float4 v0 = X4[(size_t)s0 * 32 + lane];
        ax += v0.x; ay += v0.y; az += v0.z; aw += v0.w;
    }
    ((float4*)agg)[(size_t)node * 32 + lane] = make_float4(ax, ay, az, aw);
}

// GEMM: out[n,128] = act(A)[n,128] @ W[128,128] + bias
// Inner loop uses Blackwell packed fp32 FMA (fma.rn.f32x2); BN fused on load,
// per-column stats fused in epilogue.
__global__ __launch_bounds__(256, 1)
void gemm_kernel(const float* __restrict__ A,
                 const float* __restrict__ W,
                 const float* __restrict__ bias,
                 float* __restrict__ out,
                 int n, int applyBN, int accumStats) {
    extern __shared__ float smem[];
    float* ws = smem;
    float* xs = smem + 16384;
    float4* ws4 = (float4*)ws;
    float4* xs4 = (float4*)xs;

    int tid = threadIdx.x;
    int tx = tid & 15;
    int ty = tid >> 4;
    int rowBase = blockIdx.x << 7;

    const float4* W4 = (const float4*)W;
#pragma unroll
    for (int i = 0; i < 16; i++) ws4[tid + 256 * i] = W4[tid + 256 * i];

    const float4* A4 = (const float4*)A;
#pragma unroll
    for (int i = 0; i < 16; i++) {
        int li = tid + 256 * i;
        int r = li >> 5;
        int c4 = li & 31;
        int grow = rowBase + r;
        float4 v = make_float4(0.f, 0.f, 0.f, 0.f);
        if (grow < n) v = A4[(size_t)grow * 32 + c4];
        if (applyBN) {
            float4 s = ((const float4*)(g_small + 256))[c4];
            float4 t = ((const float4*)(g_small + 384))[c4];
            v.x = fmaxf(fmaf(v.x, s.x, t.x), 0.0f);
            v.y = fmaxf(fmaf(v.y, s.y, t.y), 0.0f);
            v.z = fmaxf(fmaf(v.z, s.z, t.z), 0.0f);
            v.w = fmaxf(fmaf(v.w, s.w, t.w), 0.0f);
        }
        xs4[li] = v;
    }
    __syncthreads();

    unsigned long long acc2[8][4];
#pragma unroll
    for (int r = 0; r < 8; r++)
#pragma unroll
        for (int c = 0; c < 4; c++) acc2[r][c] = 0ull;

#pragma unroll 2
    for (int k = 0; k < 128; k += 4) {
        float a[8][4];
#pragma unroll
        for (int r = 0; r < 8; r++) {
            float4 av = xs4[(ty * 8 + r) * 32 + (k >> 2)];
            a[r][0] = av.x; a[r][1] = av.y; a[r][2] = av.z; a[r][3] = av.w;
        }
#pragma unroll
        for (int kk = 0; kk < 4; kk++) {
            float4 w0 = ws4[(k + kk) * 32 + tx];
            float4 w1 = ws4[(k + kk) * 32 + tx + 16];
            unsigned long long w2[4];
            asm("mov.b64 %0, {%1, %2};" : "=l"(w2[0]) : "f"(w0.x), "f"(w0.y));
            asm("mov.b64 %0, {%1, %2};" : "=l"(w2[1]) : "f"(w0.z), "f"(w0.w));
            asm("mov.b64 %0, {%1, %2};" : "=l"(w2[2]) : "f"(w1.x), "f"(w1.y));
            asm("mov.b64 %0, {%1, %2};" : "=l"(w2[3]) : "f"(w1.z), "f"(w1.w));
#pragma unroll
            for (int r = 0; r < 8; r++) {
                unsigned long long a2;
                asm("mov.b64 %0, {%1, %1};" : "=l"(a2) : "f"(a[r][kk]));
#pragma unroll
                for (int c = 0; c < 4; c++)
                    asm("fma.rn.f32x2 %0, %1, %2, %0;"
                        : "+l"(acc2[r][c]) : "l"(a2), "l"(w2[c]));
            }
        }
    }

    float4 b0 = ((const float4*)bias)[tx];
    float4 b1v = ((const float4*)bias)[tx + 16];
    float bv[8] = {b0.x, b0.y, b0.z, b0.w, b1v.x, b1v.y, b1v.z, b1v.w};

    float psum[8], psq[8];
#pragma unroll
    for (int c = 0; c < 8; c++) { psum[c] = 0.0f; psq[c] = 0.0f; }

#pragma unroll
    for (int r = 0; r < 8; r++) {
        int grow = rowBase + ty * 8 + r;
        if (grow < n) {
            float o[8];
#pragma unroll
            for (int c = 0; c < 4; c++) {
                float lo, hi;
                asm("mov.b64 {%0, %1}, %2;" : "=f"(lo), "=f"(hi) : "l"(acc2[r][c]));
                o[2 * c] = lo + bv[2 * c];
                o[2 * c + 1] = hi + bv[2 * c + 1];
            }
            ((float4*)out)[(size_t)grow * 32 + tx] = make_float4(o[0], o[1], o[2], o[3]);
            ((float4*)out)[(size_t)grow * 32 + tx + 16] = make_float4(o[4], o[5], o[6], o[7]);
            if (accumStats) {
#pragma unroll
                for (int c = 0; c < 8; c++) {
                    psum[c] += o[c];
                    psq[c] += o[c] * o[c];
                }
            }
        }
    }

    if (accumStats) {
        __syncthreads();
        float* redS = ws;
        float* redQ = ws + 2048;
        ((float4*)&redS[ty * 128])[tx]      = make_float4(psum[0], psum[1], psum[2], psum[3]);
        ((float4*)&redS[ty * 128])[tx + 16] = make_float4(psum[4], psum[5], psum[6], psum[7]);
        ((float4*)&redQ[ty * 128])[tx]      = make_float4(psq[0], psq[1], psq[2], psq[3]);
        ((float4*)&redQ[ty * 128])[tx + 16] = make_float4(psq[4], psq[5], psq[6], psq[7]);
        __syncthreads();
        if (tid < 128) {
            float s = 0.0f;
#pragma unroll
            for (int t = 0; t < 16; t++) s += redS[t * 128 + tid];
            atomicAdd(&g_small[tid], s);
        } else {
            int c = tid - 128;
            float q = 0.0f;
#pragma unroll
            for (int t = 0; t < 16; t++) q += redQ[t * 128 + c];
            atomicAdd(&g_small[128 + c], q);
        }
    }
}

__global__ void bnparams_kernel(const float* __restrict__ gamma,
                                const float* __restrict__ beta,
                                float invN) {
    int c = threadIdx.x;
    float mean = g_small[c] * invN;
    float var = g_small[128 + c] * invN - mean * mean;
    float sc = gamma[c] * rsqrtf(fmaxf(var, 0.0f) + 1e-5f);
    g_small[256 + c] = sc;
    g_small[384 + c] = beta[c] - mean * sc;
    g_small[c] = 0.0f;
    g_small[128 + c] = 0.0f;
}

extern "C" void kernel_launch(void* const* d_in, const int* in_sizes, int n_in,
                              void* d_out, int out_size) {
    const float* x     = (const float*)d_in[0];
    const void*  ei    = d_in[1];
    const float* eps   = (const float*)d_in[2];
    const float* W1    = (const float*)d_in[3];
    const float* b1    = (const float*)d_in[4];
    const float* g1    = (const float*)d_in[5];
    const float* beta1 = (const float*)d_in[6];
    const float* W2    = (const float*)d_in[7];
    const float* b2    = (const float*)d_in[8];
    const float* bng   = (const float*)d_in[9];
    const float* bnb   = (const float*)d_in[10];
    float* out = (float*)d_out;

    int n = in_sizes[0] / DD;
    int E = in_sizes[1] / 2;

    float* bufs = nullptr;
    cudaGetSymbolAddress((void**)&bufs, g_bufs);
    float* xn   = bufs;
    float* agg  = bufs + (size_t)1 * NMAX * DD;
    float* h    = bufs + (size_t)2 * NMAX * DD;
    float* xraw = bufs + (size_t)3 * NMAX * DD;

    cudaFuncSetAttribute((const void*)gemm_kernel,
                         cudaFuncAttributeMaxDynamicSharedMemorySize, GEMM_SMEM_BYTES);

    int nb256 = (n + 255) / 256;
    int edgeBlocks = (E + 8 * 256 - 1) / (8 * 256);   // ~8 edges/thread

    // --- one-time per launch: setup (zeros + dtype detect), CSR build ---
    setup_kernel<<<nb256, 256>>>((const int*)ei, n);
    hist_kernel<<<edgeBlocks, 256>>>(ei, E);
    scanA_kernel<<<nb256, 256>>>(n);
    scanB_kernel<<<1, 1024>>>(nb256);
    scanC2_kernel<<<nb256, 256>>>(n);
    place_kernel<<<edgeBlocks, 256>>>(ei, E);

    int prepBlocks = (n * (DD / 4) + 255) / 256;
    int aggBlocks = (n + 7) / 8;           // 8 warps/block, 1 node/warp
    int gemmBlocks = (n + 127) / 128;
    float invN = 1.0f / (float)n;

    for (int layer = 0; layer < 3; layer++) {
        const float* cur = (layer == 0) ? x : xn;
        if (layer > 0) prep_kernel<<<prepBlocks, 256>>>(xraw, xn, n);
        agg_kernel<<<aggBlocks, 256>>>(cur, agg, eps, layer, n);
        gemm_kernel<<<gemmBlocks, 256, GEMM_SMEM_BYTES>>>(
            agg, W1 + (size_t)layer * DD * DD, b1 + layer * DD, h, n, 0, 1);
        bnparams_kernel<<<1, 128>>>(g1 + layer * DD, beta1 + layer * DD, invN);
        int last = (layer == 2);
        float* o = last ? out : xraw;
        gemm_kernel<<<gemmBlocks, 256, GEMM_SMEM_BYTES>>>(
            h, W2 + (size_t)layer * DD * DD, b2 + layer * DD, o, n, 1, last ? 0 : 1);
        if (!last)
            bnparams_kernel<<<1, 128>>>(bng + layer * DD, bnb + layer * DD, invN);
    }
}